// round 15
// baseline (speedup 1.0000x reference)
#include <cuda_runtime.h>

// VolumeRenderer: fused NeRF-style compositing — FINAL (converged at the
// memory roofline; verified across 8 identical re-benches, R5/R8-R14).
// depth [R,128] f32 (sorted, in [2,6]), density [R,128] f32 (in [0,1)),
// feature [R,128,3] f32 -> out [R,4] f32 (r,g,b,depth)
//
// Configuration: 1 ray per warp, lane owns 4 consecutive samples,
// 5 front-batched LDG.128 with .cs streaming hints, Kogge-Stone warp scan,
// 11-shuffle 4-component reduction, 256-thr blocks @ 8 blocks/SM (32 regs,
// 100% theoretical occupancy).
//
// Convergence evidence (R3-R14): five structurally different schedules
// (bursty waves / 2-ray-per-warp / persistent double-buffered / 128- and
// 256-thr CTAs) all land at 5.95-6.14 TB/s HBM — the effective
// path-independent LTS/DRAM streaming ceiling on B300 for this 3-stream
// fp32 read. Traffic (161.5 MB) is irreducible -> ~26.5 us floor; this
// kernel measures 28.0-28.8 us ncu (~94% of ceiling). Noise band ±0.4 us.
//
// Numerics: exclusive scan base via shfl_up(inclusive,1) — NEVER via
// (inclusive - own), because lane 31's own partial sum contains the 1e10
// FAR_DELTA tau and fp32 cancellation (ulp(1e10)=1024) corrupts the tail
// weights (this was the R1/R2 failure).

#define FULL 0xffffffffu

__global__ __launch_bounds__(256, 8)
void vr_kernel(const float4* __restrict__ inA,   // depth OR density
               const float4* __restrict__ inB,   // the other one
               const float4* __restrict__ feature,
               float*  __restrict__ out,         // [R,4] flat
               int n_rays)
{
    // Disambiguate depth vs density by value range (depth >= 2, density < 1).
    const float probe = ((const float*)inA)[0];
    const float4* __restrict__ depth   = (probe >= 2.0f) ? inA : inB;
    const float4* __restrict__ density = (probe >= 2.0f) ? inB : inA;

    const int warp = (blockIdx.x * blockDim.x + threadIdx.x) >> 5;
    const int lane = threadIdx.x & 31;
    if (warp >= n_rays) return;

    const size_t row32 = (size_t)warp * 32;   // 128 floats = 32 float4
    const size_t row96 = (size_t)warp * 96;   // 384 floats = 96 float4

    // Lane owns samples p = 4*lane .. 4*lane+3 (5 front-batched LDG.128)
    float4 dep = __ldcs(depth   + row32 + lane);
    float4 den = __ldcs(density + row32 + lane);
    const float4* frow = feature + row96 + lane * 3;
    float4 f0 = __ldcs(frow + 0);  // {p0.r, p0.g, p0.b, p1.r}
    float4 f1 = __ldcs(frow + 1);  // {p1.g, p1.b, p2.r, p2.g}
    float4 f2 = __ldcs(frow + 2);  // {p2.b, p3.r, p3.g, p3.b}

    // deltas: depth[j+1]-depth[j]; last sample of the ray gets 1e10
    float nxt = __shfl_down_sync(FULL, dep.x, 1);
    float t0 = den.x * (dep.y - dep.x);
    float t1 = den.y * (dep.z - dep.y);
    float t2 = den.z * (dep.w - dep.z);
    float t3 = den.w * ((lane == 31) ? 1e10f : (nxt - dep.w));

    // per-lane inclusive prefix of tau
    float s0 = t0;
    float s1 = s0 + t1;
    float s2 = s1 + t2;
    float s3 = s2 + t3;   // lane 31: contains the 1e10 sentinel

    // warp inclusive scan of per-lane totals (Kogge-Stone)
    float v = s3;
    #pragma unroll
    for (int off = 1; off < 32; off <<= 1) {
        float n = __shfl_up_sync(FULL, v, off);
        if (lane >= off) v += n;
    }
    // exclusive base = previous lane's inclusive value (no subtraction ->
    // no cancellation against the sentinel term at lane 31)
    float base = __shfl_up_sync(FULL, v, 1);
    if (lane == 0) base = 0.0f;

    // w_j = exp(-excl_j) - exp(-incl_j); 5 exps per lane
    float ep = __expf(-base);
    float e0 = __expf(-(base + s0));
    float e1 = __expf(-(base + s1));
    float e2 = __expf(-(base + s2));
    float e3 = __expf(-(base + s3));   // lane31: underflows to 0
    float w0 = ep - e0, w1 = e0 - e1, w2 = e1 - e2, w3 = e2 - e3;

    // weighted accumulation (feature components per float4 packing)
    float r = w0*f0.x + w1*f0.w + w2*f1.z + w3*f2.y;
    float g = w0*f0.y + w1*f1.x + w2*f1.w + w3*f2.z;
    float b = w0*f0.z + w1*f1.y + w2*f2.x + w3*f2.w;
    float d = w0*dep.x + w1*dep.y + w2*dep.z + w3*dep.w;

    // 4-component reduction in 11 shuffles:
    // levels 1,2 on all four -> each 4-lane group holds its partials
    #pragma unroll
    for (int off = 1; off <= 2; off <<= 1) {
        r += __shfl_xor_sync(FULL, r, off);
        g += __shfl_xor_sync(FULL, g, off);
        b += __shfl_xor_sync(FULL, b, off);
        d += __shfl_xor_sync(FULL, d, off);
    }
    // each lane takes component (lane&3); 3 more levels finish all 4 sums
    int c = lane & 3;
    float val = (c == 0) ? r : (c == 1) ? g : (c == 2) ? b : d;
    #pragma unroll
    for (int off = 4; off < 32; off <<= 1)
        val += __shfl_xor_sync(FULL, val, off);

    // lanes 0..3 hold r,g,b,d totals -> one 16B line
    if (lane < 4) out[(size_t)warp * 4 + lane] = val;
}

extern "C" void kernel_launch(void* const* d_in, const int* in_sizes, int n_in,
                              void* d_out, int out_size)
{
    // feature = the (unique) largest input; remaining two disambiguated
    // in-kernel by value range.
    int fi = 2;
    for (int i = 0; i < 3; ++i)
        if (in_sizes[i] > in_sizes[(i + 1) % 3] && in_sizes[i] > in_sizes[(i + 2) % 3]) fi = i;
    int a = (fi == 0) ? 1 : 0;
    int b = (fi == 2) ? 1 : 2;
    if (b == fi || b == a) b = 3 - a - fi;

    const float4* inA     = (const float4*)d_in[a];
    const float4* inB     = (const float4*)d_in[b];
    const float4* feature = (const float4*)d_in[fi];
    float* out = (float*)d_out;

    int n_rays = in_sizes[a] / 128;
    int blocks = (n_rays + 7) / 8;   // 8 warps (rays) per 256-thread block
    vr_kernel<<<blocks, 256>>>(inA, inB, feature, out, n_rays);
}

// round 16
// speedup vs baseline: 1.0011x; 1.0011x over previous
#include <cuda_runtime.h>

// VolumeRenderer: fused NeRF-style compositing — FINAL (converged at the
// memory roofline; verified across 9 identical re-benches, R5/R8-R15).
// depth [R,128] f32 (sorted, in [2,6]), density [R,128] f32 (in [0,1)),
// feature [R,128,3] f32 -> out [R,4] f32 (r,g,b,depth)
//
// Configuration: 1 ray per warp, lane owns 4 consecutive samples,
// 5 front-batched LDG.128 with .cs streaming hints, Kogge-Stone warp scan,
// 11-shuffle 4-component reduction, 256-thr blocks @ 8 blocks/SM (32 regs,
// 100% theoretical occupancy).
//
// Convergence evidence (R3-R15): five structurally different schedules
// (bursty waves / 2-ray-per-warp / persistent double-buffered / 128- and
// 256-thr CTAs) all land at 5.91-6.14 TB/s HBM — the effective
// path-independent LTS/DRAM streaming ceiling on B300 for this 3-stream
// fp32 read. Traffic (161.5 MB) is irreducible -> ~26.5 us floor; this
// kernel measures 28.0-29.0 us ncu (~94% of ceiling). Noise band ±0.4 us.
//
// Numerics: exclusive scan base via shfl_up(inclusive,1) — NEVER via
// (inclusive - own), because lane 31's own partial sum contains the 1e10
// FAR_DELTA tau and fp32 cancellation (ulp(1e10)=1024) corrupts the tail
// weights (this was the R1/R2 failure).

#define FULL 0xffffffffu

__global__ __launch_bounds__(256, 8)
void vr_kernel(const float4* __restrict__ inA,   // depth OR density
               const float4* __restrict__ inB,   // the other one
               const float4* __restrict__ feature,
               float*  __restrict__ out,         // [R,4] flat
               int n_rays)
{
    // Disambiguate depth vs density by value range (depth >= 2, density < 1).
    const float probe = ((const float*)inA)[0];
    const float4* __restrict__ depth   = (probe >= 2.0f) ? inA : inB;
    const float4* __restrict__ density = (probe >= 2.0f) ? inB : inA;

    const int warp = (blockIdx.x * blockDim.x + threadIdx.x) >> 5;
    const int lane = threadIdx.x & 31;
    if (warp >= n_rays) return;

    const size_t row32 = (size_t)warp * 32;   // 128 floats = 32 float4
    const size_t row96 = (size_t)warp * 96;   // 384 floats = 96 float4

    // Lane owns samples p = 4*lane .. 4*lane+3 (5 front-batched LDG.128)
    float4 dep = __ldcs(depth   + row32 + lane);
    float4 den = __ldcs(density + row32 + lane);
    const float4* frow = feature + row96 + lane * 3;
    float4 f0 = __ldcs(frow + 0);  // {p0.r, p0.g, p0.b, p1.r}
    float4 f1 = __ldcs(frow + 1);  // {p1.g, p1.b, p2.r, p2.g}
    float4 f2 = __ldcs(frow + 2);  // {p2.b, p3.r, p3.g, p3.b}

    // deltas: depth[j+1]-depth[j]; last sample of the ray gets 1e10
    float nxt = __shfl_down_sync(FULL, dep.x, 1);
    float t0 = den.x * (dep.y - dep.x);
    float t1 = den.y * (dep.z - dep.y);
    float t2 = den.z * (dep.w - dep.z);
    float t3 = den.w * ((lane == 31) ? 1e10f : (nxt - dep.w));

    // per-lane inclusive prefix of tau
    float s0 = t0;
    float s1 = s0 + t1;
    float s2 = s1 + t2;
    float s3 = s2 + t3;   // lane 31: contains the 1e10 sentinel

    // warp inclusive scan of per-lane totals (Kogge-Stone)
    float v = s3;
    #pragma unroll
    for (int off = 1; off < 32; off <<= 1) {
        float n = __shfl_up_sync(FULL, v, off);
        if (lane >= off) v += n;
    }
    // exclusive base = previous lane's inclusive value (no subtraction ->
    // no cancellation against the sentinel term at lane 31)
    float base = __shfl_up_sync(FULL, v, 1);
    if (lane == 0) base = 0.0f;

    // w_j = exp(-excl_j) - exp(-incl_j); 5 exps per lane
    float ep = __expf(-base);
    float e0 = __expf(-(base + s0));
    float e1 = __expf(-(base + s1));
    float e2 = __expf(-(base + s2));
    float e3 = __expf(-(base + s3));   // lane31: underflows to 0
    float w0 = ep - e0, w1 = e0 - e1, w2 = e1 - e2, w3 = e2 - e3;

    // weighted accumulation (feature components per float4 packing)
    float r = w0*f0.x + w1*f0.w + w2*f1.z + w3*f2.y;
    float g = w0*f0.y + w1*f1.x + w2*f1.w + w3*f2.z;
    float b = w0*f0.z + w1*f1.y + w2*f2.x + w3*f2.w;
    float d = w0*dep.x + w1*dep.y + w2*dep.z + w3*dep.w;

    // 4-component reduction in 11 shuffles:
    // levels 1,2 on all four -> each 4-lane group holds its partials
    #pragma unroll
    for (int off = 1; off <= 2; off <<= 1) {
        r += __shfl_xor_sync(FULL, r, off);
        g += __shfl_xor_sync(FULL, g, off);
        b += __shfl_xor_sync(FULL, b, off);
        d += __shfl_xor_sync(FULL, d, off);
    }
    // each lane takes component (lane&3); 3 more levels finish all 4 sums
    int c = lane & 3;
    float val = (c == 0) ? r : (c == 1) ? g : (c == 2) ? b : d;
    #pragma unroll
    for (int off = 4; off < 32; off <<= 1)
        val += __shfl_xor_sync(FULL, val, off);

    // lanes 0..3 hold r,g,b,d totals -> one 16B line
    if (lane < 4) out[(size_t)warp * 4 + lane] = val;
}

extern "C" void kernel_launch(void* const* d_in, const int* in_sizes, int n_in,
                              void* d_out, int out_size)
{
    // feature = the (unique) largest input; remaining two disambiguated
    // in-kernel by value range.
    int fi = 2;
    for (int i = 0; i < 3; ++i)
        if (in_sizes[i] > in_sizes[(i + 1) % 3] && in_sizes[i] > in_sizes[(i + 2) % 3]) fi = i;
    int a = (fi == 0) ? 1 : 0;
    int b = (fi == 2) ? 1 : 2;
    if (b == fi || b == a) b = 3 - a - fi;

    const float4* inA     = (const float4*)d_in[a];
    const float4* inB     = (const float4*)d_in[b];
    const float4* feature = (const float4*)d_in[fi];
    float* out = (float*)d_out;

    int n_rays = in_sizes[a] / 128;
    int blocks = (n_rays + 7) / 8;   // 8 warps (rays) per 256-thread block
    vr_kernel<<<blocks, 256>>>(inA, inB, feature, out, n_rays);
}